// round 7
// baseline (speedup 1.0000x reference)
#include <cuda_runtime.h>
#include <cuda_bf16.h>
#include <math.h>
#include <stdint.h>

#define BB 4
#define NN 384
#define DD 64
#define NTH 256

// k16 steps: G1 kk0-15 (hs@W1a | |hs-ht|@W1b | hs@(diag(ht)W1c) | e@W1d),
// G2 kk16-19, G3 kk20-27 (e, de), G4 kk28-35 (hs, e_new).
// ht@W1a and ht@Wm[64:128] folded into biases.
#define KK_TOTAL 36
#define NFRAG 8
__device__ uint4 g_Wf[KK_TOTAL * NFRAG * 32];

#define SWF_U4   (KK_TOTAL * NFRAG * 32)        // 9216 uint4
#define OFF_B1P  (SWF_U4 * 4)
#define OFF_B2   (OFF_B1P + 64)
#define OFF_BG   (OFF_B2 + 64)
#define OFF_BMP  (OFF_BG + 64)
#define OFF_SHI  (OFF_BMP + 64)
#define OFF_RED  (OFF_SHI + 64)                 // 512
#define OFF_XS   (OFF_RED + 512)                // 128
#define OFF_DHS  (OFF_XS + 128)                 // 64
#define SMEM_U32 (OFF_DHS + 64)
#define SMEM_BYTES (SMEM_U32 * 4)

__device__ __forceinline__ float fsig(float x) { return 1.0f / (1.0f + __expf(-x)); }
__device__ __forceinline__ float fsilu(float x) { return x * fsig(x); }

// fast split: hi = bf16x2(v1,v0); lo = bf16x2(residuals)
__device__ __forceinline__ void splitpk(float v0, float v1, unsigned &whi, unsigned &wlo) {
    unsigned ph;
    asm("cvt.rn.bf16x2.f32 %0, %1, %2;" : "=r"(ph) : "f"(v1), "f"(v0));
    float f0 = __uint_as_float(ph << 16);
    float f1 = __uint_as_float(ph & 0xffff0000u);
    asm("cvt.rn.bf16x2.f32 %0, %1, %2;" : "=r"(wlo) : "f"(v1 - f1), "f"(v0 - f0));
    whi = ph;
}
__device__ __forceinline__ void up2(unsigned w, float &f0, float &f1) {
    f0 = __uint_as_float(w << 16);
    f1 = __uint_as_float(w & 0xffff0000u);
}

__device__ __forceinline__ void mma4(float *d, const unsigned *a, unsigned b0, unsigned b1) {
    asm("mma.sync.aligned.m16n8k16.row.col.f32.bf16.bf16.f32 "
        "{%0,%1,%2,%3}, {%4,%5,%6,%7}, {%8,%9}, {%0,%1,%2,%3};"
        : "+f"(d[0]), "+f"(d[1]), "+f"(d[2]), "+f"(d[3])
        : "r"(a[0]), "r"(a[1]), "r"(a[2]), "r"(a[3]), "r"(b0), "r"(b1));
}
__device__ __forceinline__ void mma3(float *d, const unsigned *ah, const unsigned *al, uint4 b) {
    mma4(d, ah, b.x, b.y);
    mma4(d, al, b.x, b.y);
    mma4(d, ah, b.z, b.w);
}

// ---- prep: pack weight B-fragments (hi/lo bf16) ----
__global__ void prep_kernel(const float *__restrict__ W1, const float *__restrict__ W2,
                            const float *__restrict__ Wg, const float *__restrict__ Wm)
{
    const int kk = blockIdx.x;
    const int tid = threadIdx.x;
    const int f = tid >> 5;
    const int lane = tid & 31;
    const int g = lane >> 2;
    const int t = lane & 3;
    const int n = 8 * f + g;

    const float *W; int kb;
    if (kk < 16)      { W = W1; kb = kk * 16; }
    else if (kk < 20) { W = W2; kb = (kk - 16) * 16; }
    else if (kk < 28) { W = Wg; kb = (kk - 20) * 16; }
    else if (kk < 32) { W = Wm; kb = (kk - 28) * 16; }
    else              { W = Wm; kb = 128 + (kk - 32) * 16; }

    float w0 = W[(kb + 2 * t) * 64 + n];
    float w1 = W[(kb + 2 * t + 1) * 64 + n];
    float w2 = W[(kb + 2 * t + 8) * 64 + n];
    float w3 = W[(kb + 2 * t + 9) * 64 + n];
    unsigned h0, l0, h1, l1;
    splitpk(w0, w1, h0, l0);
    splitpk(w2, w3, h1, l1);
    g_Wf[(kk * NFRAG + f) * 32 + lane] = make_uint4(h0, h1, l0, l1);
}

__global__ void __launch_bounds__(NTH, 1) edge_kernel(
    const float *__restrict__ h, const float *__restrict__ e,
    const float *__restrict__ W1, const float *__restrict__ b1,
    const float *__restrict__ b2, const float *__restrict__ bg,
    const float *__restrict__ bm, const float *__restrict__ Wm,
    const float *__restrict__ Wu, const float *__restrict__ bu,
    const float *__restrict__ Wg2, const float *__restrict__ bg2,
    float *__restrict__ h_out, float *__restrict__ e_out)
{
    extern __shared__ unsigned smu[];
    uint4 *sWfm = (uint4 *)smu;
    const uint4 *sWf = (const uint4 *)smu;
    float *sb1p = (float *)(smu + OFF_B1P);
    float *sb2 = (float *)(smu + OFF_B2);
    float *sbg = (float *)(smu + OFF_BG);
    float *sbmp = (float *)(smu + OFF_BMP);
    float *shi = (float *)(smu + OFF_SHI);
    float *sred = (float *)(smu + OFF_RED);
    float *sxs = (float *)(smu + OFF_XS);
    float *sdh = (float *)(smu + OFF_DHS);

    const int tid = threadIdx.x;
    const int w = tid >> 5;
    const int lane = tid & 31;
    const int g = lane >> 2;
    const int t = lane & 3;

    const int blk = blockIdx.x;
    const int b = blk / NN;
    const int i = blk - b * NN;
    const size_t erow = ((size_t)(b * NN + i)) * NN;
    const int node = b * NN + i;

    // ---- stage weights + h_i + plain biases ----
    for (int idx = tid; idx < SWF_U4; idx += NTH) sWfm[idx] = g_Wf[idx];
    if (tid < 64) {
        shi[tid] = h[node * DD + tid];
        sb2[tid] = b2[tid];
        sbg[tid] = bg[tid];
    }
    __syncthreads();

    // ---- per-block weight transform: kk 8-11 -> diag(ht) * W1c ----
#pragma unroll
    for (int p = 0; p < 4; p++) {
        const int idx = 2048 + tid + p * NTH;   // [2048, 3072)
        uint4 v = sWfm[idx];
        const int t_ = idx & 3;
        const int kk_ = idx >> 8;               // 8..11
        const int kl = (kk_ - 8) * 16 + 2 * t_;
        float w0, w1, w2, w3, x0, x1, x2, x3;
        up2(v.x, w0, w1); up2(v.z, x0, x1); w0 += x0; w1 += x1;
        up2(v.y, w2, w3); up2(v.w, x2, x3); w2 += x2; w3 += x3;
        unsigned h0, l0, h1, l1;
        splitpk(w0 * shi[kl], w1 * shi[kl + 1], h0, l0);
        splitpk(w2 * shi[kl + 8], w3 * shi[kl + 9], h1, l1);
        sWfm[idx] = make_uint4(h0, h1, l0, l1);
    }
    // ---- bias folds: b1' = b1 + ht@W1[0:64];  bm' = bm + ht@Wm[64:128] ----
    if (tid < 128) {
        const int c = tid & 63;
        if (tid < 64) {
            float a = b1[c];
#pragma unroll 8
            for (int k = 0; k < 64; k++) a = fmaf(shi[k], W1[k * 64 + c], a);
            sb1p[c] = a;
        } else {
            float a = bm[c];
#pragma unroll 8
            for (int k = 0; k < 64; k++) a = fmaf(shi[k], Wm[(64 + k) * 64 + c], a);
            sbmp[c] = a;
        }
    }
    __syncthreads();

    // ht at owned cols
    float2 htv[4][2];
#pragma unroll
    for (int m = 0; m < 4; m++)
#pragma unroll
        for (int p = 0; p < 2; p++)
            htv[m][p] = *(const float2 *)&shi[16 * m + 8 * p + 2 * t];

    float2 aggc[8];
#pragma unroll
    for (int f = 0; f < 8; f++) aggc[f] = make_float2(0.f, 0.f);

    for (int j0 = 0; j0 < NN; j0 += 128) {
        const int rA = j0 + 16 * w + g;
        const int rB = rA + 8;
        const float *hA = &h[(b * NN + rA) * DD];
        const float *hB = &h[(b * NN + rB) * DD];
        const float *epA = &e[(erow + rA) * DD];
        const float *epB = &e[(erow + rB) * DD];

        // ---- load + split hs, |hs-ht|, e ----
        unsigned hsFh[4][4], hsFl[4][4], dFh[4][4], dFl[4][4], eFh[4][4], eFl[4][4];
#pragma unroll
        for (int m = 0; m < 4; m++)
#pragma unroll
            for (int p = 0; p < 2; p++) {
                const int c = 16 * m + 8 * p + 2 * t;
                const float2 ht2 = htv[m][p];
                float2 a = *(const float2 *)&hA[c];
                float2 bv = *(const float2 *)&hB[c];
                splitpk(a.x, a.y, hsFh[m][2 * p], hsFl[m][2 * p]);
                splitpk(bv.x, bv.y, hsFh[m][2 * p + 1], hsFl[m][2 * p + 1]);
                splitpk(fabsf(a.x - ht2.x), fabsf(a.y - ht2.y), dFh[m][2 * p], dFl[m][2 * p]);
                splitpk(fabsf(bv.x - ht2.x), fabsf(bv.y - ht2.y), dFh[m][2 * p + 1], dFl[m][2 * p + 1]);
                float2 ev = *(const float2 *)&epA[c];
                float2 ew = *(const float2 *)&epB[c];
                splitpk(ev.x, ev.y, eFh[m][2 * p], eFl[m][2 * p]);
                splitpk(ew.x, ew.y, eFh[m][2 * p + 1], eFl[m][2 * p + 1]);
            }

        // ---- G1: D = hs@W1a + d@W1b + hs@W1c' + e@W1d ----
        float D[8][4];
#pragma unroll
        for (int f = 0; f < 8; f++) { D[f][0] = D[f][1] = D[f][2] = D[f][3] = 0.f; }
#pragma unroll
        for (int m = 0; m < 4; m++)
#pragma unroll
            for (int f = 0; f < 8; f++)
                mma3(D[f], hsFh[m], hsFl[m], sWf[(m * NFRAG + f) * 32 + lane]);
#pragma unroll
        for (int m = 0; m < 4; m++)
#pragma unroll
            for (int f = 0; f < 8; f++)
                mma3(D[f], dFh[m], dFl[m], sWf[((4 + m) * NFRAG + f) * 32 + lane]);
#pragma unroll
        for (int m = 0; m < 4; m++)
#pragma unroll
            for (int f = 0; f < 8; f++)
                mma3(D[f], hsFh[m], hsFl[m], sWf[((8 + m) * NFRAG + f) * 32 + lane]);
#pragma unroll
        for (int m = 0; m < 4; m++)
#pragma unroll
            for (int f = 0; f < 8; f++)
                mma3(D[f], eFh[m], eFl[m], sWf[((12 + m) * NFRAG + f) * 32 + lane]);

        // ---- t1 = silu(D + b1') ----
        unsigned t1h[4][4], t1l[4][4];
#pragma unroll
        for (int m = 0; m < 4; m++) {
            const int f0 = 2 * m, f1 = 2 * m + 1;
            float2 bb0 = *(const float2 *)&sb1p[8 * f0 + 2 * t];
            float2 bb1 = *(const float2 *)&sb1p[8 * f1 + 2 * t];
            splitpk(fsilu(D[f0][0] + bb0.x), fsilu(D[f0][1] + bb0.y), t1h[m][0], t1l[m][0]);
            splitpk(fsilu(D[f0][2] + bb0.x), fsilu(D[f0][3] + bb0.y), t1h[m][1], t1l[m][1]);
            splitpk(fsilu(D[f1][0] + bb1.x), fsilu(D[f1][1] + bb1.y), t1h[m][2], t1l[m][2]);
            splitpk(fsilu(D[f1][2] + bb1.x), fsilu(D[f1][3] + bb1.y), t1h[m][3], t1l[m][3]);
        }

        // ---- G2: D2 = t1 @ W2 + b2 ----
        float D2[8][4];
#pragma unroll
        for (int f = 0; f < 8; f++) { D2[f][0] = D2[f][1] = D2[f][2] = D2[f][3] = 0.f; }
#pragma unroll
        for (int kk = 0; kk < 4; kk++)
#pragma unroll
            for (int f = 0; f < 8; f++)
                mma3(D2[f], t1h[kk], t1l[kk], sWf[((16 + kk) * NFRAG + f) * 32 + lane]);
#pragma unroll
        for (int f = 0; f < 8; f++) {
            float2 bb = *(const float2 *)&sb2[8 * f + 2 * t];
            D2[f][0] += bb.x; D2[f][1] += bb.y; D2[f][2] += bb.x; D2[f][3] += bb.y;
        }
        // de frags (reuse t1 regs)
#pragma unroll
        for (int kk = 0; kk < 4; kk++) {
            splitpk(D2[2 * kk][0], D2[2 * kk][1], t1h[kk][0], t1l[kk][0]);
            splitpk(D2[2 * kk][2], D2[2 * kk][3], t1h[kk][1], t1l[kk][1]);
            splitpk(D2[2 * kk + 1][0], D2[2 * kk + 1][1], t1h[kk][2], t1l[kk][2]);
            splitpk(D2[2 * kk + 1][2], D2[2 * kk + 1][3], t1h[kk][3], t1l[kk][3]);
        }

        // ---- G3: D3 = [e, de] @ Wg ----
        float D3[8][4];
#pragma unroll
        for (int f = 0; f < 8; f++) { D3[f][0] = D3[f][1] = D3[f][2] = D3[f][3] = 0.f; }
#pragma unroll
        for (int kk = 0; kk < 4; kk++)
#pragma unroll
            for (int f = 0; f < 8; f++)
                mma3(D3[f], eFh[kk], eFl[kk], sWf[((20 + kk) * NFRAG + f) * 32 + lane]);
#pragma unroll
        for (int kk = 0; kk < 4; kk++)
#pragma unroll
            for (int f = 0; f < 8; f++)
                mma3(D3[f], t1h[kk], t1l[kk], sWf[((24 + kk) * NFRAG + f) * 32 + lane]);

        // ---- e_new = sig(D3+bg)*e + (1-sig)*de; store; refill eF with e_new ----
        float *eoA = &e_out[(erow + rA) * DD];
        float *eoB = &e_out[(erow + rB) * DD];
#pragma unroll
        for (int m = 0; m < 4; m++)
#pragma unroll
            for (int p = 0; p < 2; p++) {
                const int f = 2 * m + p;
                float2 bb = *(const float2 *)&sbg[8 * f + 2 * t];
                float ea0, ea1, xa0, xa1, eb0, eb1, xb0, xb1;
                up2(eFh[m][2 * p], ea0, ea1); up2(eFl[m][2 * p], xa0, xa1);
                up2(eFh[m][2 * p + 1], eb0, eb1); up2(eFl[m][2 * p + 1], xb0, xb1);
                ea0 += xa0; ea1 += xa1; eb0 += xb0; eb1 += xb1;
                float g0 = fsig(D3[f][0] + bb.x), g1 = fsig(D3[f][1] + bb.y);
                float g2 = fsig(D3[f][2] + bb.x), g3 = fsig(D3[f][3] + bb.y);
                float2 nA, nB;
                nA.x = g0 * ea0 + (1.f - g0) * D2[f][0];
                nA.y = g1 * ea1 + (1.f - g1) * D2[f][1];
                nB.x = g2 * eb0 + (1.f - g2) * D2[f][2];
                nB.y = g3 * eb1 + (1.f - g3) * D2[f][3];
                const int c = 16 * m + 8 * p + 2 * t;
                *(float2 *)&eoA[c] = nA;
                *(float2 *)&eoB[c] = nB;
                splitpk(nA.x, nA.y, eFh[m][2 * p], eFl[m][2 * p]);
                splitpk(nB.x, nB.y, eFh[m][2 * p + 1], eFl[m][2 * p + 1]);
            }

        // ---- G4: D4 = [hs, e_new] @ Wm' ----
        float D4[8][4];
#pragma unroll
        for (int f = 0; f < 8; f++) { D4[f][0] = D4[f][1] = D4[f][2] = D4[f][3] = 0.f; }
#pragma unroll
        for (int kk = 0; kk < 4; kk++)
#pragma unroll
            for (int f = 0; f < 8; f++)
                mma3(D4[f], hsFh[kk], hsFl[kk], sWf[((28 + kk) * NFRAG + f) * 32 + lane]);
#pragma unroll
        for (int kk = 0; kk < 4; kk++)
#pragma unroll
            for (int f = 0; f < 8; f++)
                mma3(D4[f], eFh[kk], eFl[kk], sWf[((32 + kk) * NFRAG + f) * 32 + lane]);

        // ---- msg = silu(D4 + bm'), mask diagonal, accumulate ----
        const bool mA = (rA != i), mB = (rB != i);
#pragma unroll
        for (int f = 0; f < 8; f++) {
            float2 bb = *(const float2 *)&sbmp[8 * f + 2 * t];
            float m0 = fsilu(D4[f][0] + bb.x), m1 = fsilu(D4[f][1] + bb.y);
            float m2 = fsilu(D4[f][2] + bb.x), m3 = fsilu(D4[f][3] + bb.y);
            aggc[f].x += (mA ? m0 : 0.f) + (mB ? m2 : 0.f);
            aggc[f].y += (mA ? m1 : 0.f) + (mB ? m3 : 0.f);
        }
    }

    // ---- agg reduce ----
#pragma unroll
    for (int f = 0; f < 8; f++) {
        float x = aggc[f].x, y = aggc[f].y;
        x += __shfl_xor_sync(0xffffffffu, x, 4);
        x += __shfl_xor_sync(0xffffffffu, x, 8);
        x += __shfl_xor_sync(0xffffffffu, x, 16);
        y += __shfl_xor_sync(0xffffffffu, y, 4);
        y += __shfl_xor_sync(0xffffffffu, y, 8);
        y += __shfl_xor_sync(0xffffffffu, y, 16);
        aggc[f].x = x; aggc[f].y = y;
    }
    if (lane < 4) {
#pragma unroll
        for (int f = 0; f < 8; f++) {
            sred[w * 64 + 8 * f + 2 * lane] = aggc[f].x;
            sred[w * 64 + 8 * f + 2 * lane + 1] = aggc[f].y;
        }
    }
    __syncthreads();

    // ---- fused node update ----
    if (tid < 64) {
        float s = 0.f;
#pragma unroll
        for (int ww = 0; ww < 8; ww++) s += sred[ww * 64 + tid];
        sxs[tid] = shi[tid];
        sxs[64 + tid] = s * (1.0f / (NN - 1));
    }
    __syncthreads();
    float dh = 0.f;
    if (tid < 64) {
        float acc = bu[tid];
#pragma unroll 8
        for (int k = 0; k < 128; k++) acc = fmaf(sxs[k], Wu[k * 64 + tid], acc);
        dh = fsilu(acc);
        sdh[tid] = dh;
    }
    __syncthreads();
    if (tid < 64) {
        float a2 = bg2[tid];
#pragma unroll 8
        for (int k = 0; k < 64; k++) a2 = fmaf(sxs[k], Wg2[k * 64 + tid], a2);
#pragma unroll 8
        for (int k = 0; k < 64; k++) a2 = fmaf(sdh[k], Wg2[(64 + k) * 64 + tid], a2);
        float gg = fsig(a2);
        h_out[node * DD + tid] = gg * sxs[tid] + (1.0f - gg) * dh;
    }
}

extern "C" void kernel_launch(void* const* d_in, const int* in_sizes, int n_in,
                              void* d_out, int out_size)
{
    const float* h   = (const float*)d_in[0];
    const float* e   = (const float*)d_in[1];
    const float* W1  = (const float*)d_in[2];
    const float* b1  = (const float*)d_in[3];
    const float* W2  = (const float*)d_in[4];
    const float* b2  = (const float*)d_in[5];
    const float* Weg = (const float*)d_in[6];
    const float* beg = (const float*)d_in[7];
    const float* Wm  = (const float*)d_in[8];
    const float* bm  = (const float*)d_in[9];
    const float* Wu  = (const float*)d_in[10];
    const float* bu  = (const float*)d_in[11];
    const float* Wga = (const float*)d_in[12];
    const float* bga = (const float*)d_in[13];

    float* out = (float*)d_out;
    float* h_out = out;                       // (B,N,D)
    float* e_out = out + BB * NN * DD;        // (B,N,N,D)

    cudaFuncSetAttribute(edge_kernel, cudaFuncAttributeMaxDynamicSharedMemorySize, SMEM_BYTES);

    prep_kernel<<<KK_TOTAL, NTH>>>(W1, W2, Weg, Wm);
    edge_kernel<<<BB * NN, NTH, SMEM_BYTES>>>(h, e, W1, b1, b2, beg, bm, Wm,
                                              Wu, bu, Wga, bga, h_out, e_out);
}